// round 1
// baseline (speedup 1.0000x reference)
#include <cuda_runtime.h>
#include <math.h>

#define Bb 64
#define Tt 12
#define Nn 512
#define Dd 2
#define Rr 64
#define Mm 64
#define NB (Nn*Bb)   // 32768 rows (node-major: row = n*64 + b)

// -------- device scratch (no allocations allowed) --------
__device__ float g_h[2][NB*Rr];      // ping-pong hidden state, 2 x 8MB
__device__ float g_out1[NB*256];     // per-row [gh(192) | hw(64)]
__device__ float g_m[NB*Mm];         // aggregated messages
__device__ float g_WcT[64*256];      // [k][o] : o<192 -> W_hh, o>=192 -> W_msg
__device__ float g_bc[256];          // [b_hh | b_msg]
__device__ float g_WihT[66*192];     // [k][o]
__device__ int   g_colj[Nn*Nn];      // CSC, strided: column i at [i*512 ..]
__device__ float g_colw[Nn*Nn];
__device__ int   g_cnt[Nn];

// -------- once-per-launch prep --------
__global__ void prep_weights(const float* __restrict__ W_msg,
                             const float* __restrict__ b_msg,
                             const float* __restrict__ W_ih,
                             const float* __restrict__ W_hh,
                             const float* __restrict__ b_hh) {
    int idx = blockIdx.x * 256 + threadIdx.x;
    if (idx < 16384) {
        int k = idx >> 8, o = idx & 255;
        g_WcT[k*256 + o] = (o < 192) ? W_hh[o*64 + k] : W_msg[(o-192)*64 + k];
    } else if (idx < 16384 + 12672) {
        int j = idx - 16384;
        int k = j / 192, o = j - k*192;
        g_WihT[k*192 + o] = W_ih[o*66 + k];
    } else if (idx < 16384 + 12672 + 256) {
        int o = idx - 16384 - 12672;
        g_bc[o] = (o < 192) ? b_hh[o] : b_msg[o-192];
    }
}

// Deterministic CSC build: one block per column i, ballot+popc compaction
// preserves j-order, so downstream fp accumulation order is fixed.
__global__ void build_csc(const float* __restrict__ adj) {
    int i = blockIdx.x;
    int j = threadIdx.x;                      // 512 threads
    float w = adj[j*Nn + i];
    bool p = (w > 0.f);
    unsigned mask = __ballot_sync(0xffffffffu, p);
    int warp = j >> 5, lane = j & 31;
    __shared__ int wcnt[16];
    __shared__ int wofs[16];
    if (lane == 0) wcnt[warp] = __popc(mask);
    __syncthreads();
    if (j == 0) {
        int s = 0;
        for (int t = 0; t < 16; t++) { wofs[t] = s; s += wcnt[t]; }
        g_cnt[i] = s;
    }
    __syncthreads();
    if (p) {
        int pos = wofs[warp] + __popc(mask & ((1u << lane) - 1u));
        g_colj[i*Nn + pos] = j;
        g_colw[i*Nn + pos] = w;
    }
}

__global__ void copy_h0(const float* __restrict__ h0) {
    int idx = blockIdx.x * 256 + threadIdx.x;
    if (idx < NB * Rr) g_h[0][idx] = h0[idx];
}

// -------- per-step kernel 1: out1[row][0..255] = h[row] @ WcT + bc --------
// grid (256, 2), 256 threads; block tile = 128 rows x 128 outs; K = 64.
__global__ void gemm1_kernel(int cur) {
    extern __shared__ float sm[];
    float* hS = sm;                  // [128][68] padded
    float* wS = sm + 128*68;         // [64][128]
    int rowBase = blockIdx.x * 128;
    int oBase   = blockIdx.y * 128;
    int tid = threadIdx.x;
    const float* __restrict__ hcur = g_h[cur];

    for (int idx = tid; idx < 8192; idx += 256) {
        int r = idx >> 6, k = idx & 63;
        hS[r*68 + k] = hcur[(rowBase + r)*64 + k];
    }
    for (int idx = tid; idx < 8192; idx += 256) {
        int k = idx >> 7, o = idx & 127;
        wS[k*128 + o] = g_WcT[k*256 + oBase + o];
    }
    __syncthreads();

    int tx = tid & 15, ty = tid >> 4;
    float acc[8][8];
    #pragma unroll
    for (int i = 0; i < 8; i++)
        #pragma unroll
        for (int j = 0; j < 8; j++) acc[i][j] = 0.f;

    #pragma unroll 4
    for (int k = 0; k < 64; k++) {
        float4 w0 = *(const float4*)(wS + k*128 + tx*8);
        float4 w1 = *(const float4*)(wS + k*128 + tx*8 + 4);
        #pragma unroll
        for (int i = 0; i < 8; i++) {
            float hv = hS[(ty*8 + i)*68 + k];
            acc[i][0] += hv * w0.x;  acc[i][1] += hv * w0.y;
            acc[i][2] += hv * w0.z;  acc[i][3] += hv * w0.w;
            acc[i][4] += hv * w1.x;  acc[i][5] += hv * w1.y;
            acc[i][6] += hv * w1.z;  acc[i][7] += hv * w1.w;
        }
    }
    #pragma unroll
    for (int i = 0; i < 8; i++) {
        int row = rowBase + ty*8 + i;
        float* dst = g_out1 + row*256 + oBase + tx*8;
        #pragma unroll
        for (int j = 0; j < 8; j++)
            dst[j] = acc[i][j] + g_bc[oBase + tx*8 + j];
    }
}

// -------- per-step kernel 2: sparse aggregation --------
// block = (batch b, 32-wide m-chunk mc). Stage hw[:, b, chunk] in smem,
// each warp owns a set of columns i (sequential, deterministic accumulation).
__global__ void agg_kernel() {
    extern __shared__ float hwS[];   // [512][32]
    int bm = blockIdx.x;             // 0..127
    int b = bm & 63, mc = bm >> 6;
    int tid = threadIdx.x;

    for (int idx = tid; idx < Nn*32; idx += 256) {
        int j = idx >> 5, mm = idx & 31;
        hwS[idx] = g_out1[((j << 6) + b)*256 + 192 + (mc << 5) + mm];
    }
    __syncthreads();

    int lane = tid & 31, wid = tid >> 5;
    for (int i = wid; i < Nn; i += 8) {
        int cnt = g_cnt[i];
        const int*   cj = g_colj + i*Nn;
        const float* cw = g_colw + i*Nn;
        float acc = 0.f;
        for (int e0 = 0; e0 < cnt; e0 += 32) {
            int ee = e0 + lane;
            int   jv = (ee < cnt) ? cj[ee] : 0;
            float wv = (ee < cnt) ? cw[ee] : 0.f;
            int lim = min(32, cnt - e0);
            for (int kk = 0; kk < lim; kk++) {
                int   j = __shfl_sync(0xffffffffu, jv, kk);
                float w = __shfl_sync(0xffffffffu, wv, kk);
                acc += w * hwS[j*32 + lane];
            }
        }
        g_m[((i << 6) + b)*64 + (mc << 5) + lane] = acc;
    }
}

// -------- per-step kernel 3: gi GEMM + GRU update --------
// grid 512 (64 rows each), 256 threads (16x16); thread computes 4 rows x
// 4 gate-indices x 3 gates so the GRU nonlinearity fuses in-register.
__global__ void gates_kernel(const float* __restrict__ inputs,
                             const float* __restrict__ b_ih,
                             int t, int cur) {
    extern __shared__ float sm[];
    float* WihS = sm;                 // 66*192 = 12672
    float* mS   = sm + 12672;         // [64][68] padded
    int rowBase = blockIdx.x * 64;
    int tid = threadIdx.x;

    for (int idx = tid; idx < 66*192; idx += 256) WihS[idx] = g_WihT[idx];
    for (int idx = tid; idx < 4096; idx += 256) {
        int r = idx >> 6, k = idx & 63;
        mS[r*68 + k] = g_m[(rowBase + r)*64 + k];
    }
    __syncthreads();

    int tx = tid & 15, ty = tid >> 4;
    float acc[4][12];
    #pragma unroll
    for (int rr = 0; rr < 4; rr++)
        #pragma unroll
        for (int q = 0; q < 12; q++) acc[rr][q] = 0.f;

    #pragma unroll 4
    for (int k = 0; k < 64; k++) {
        const float* wk = WihS + k*192;
        float mv[4];
        #pragma unroll
        for (int rr = 0; rr < 4; rr++) mv[rr] = mS[(ty*4 + rr)*68 + k];
        #pragma unroll
        for (int q = 0; q < 4; q++) {
            int g = tx + q*16;
            float wr = wk[g], wz = wk[64 + g], wn = wk[128 + g];
            #pragma unroll
            for (int rr = 0; rr < 4; rr++) {
                acc[rr][q*3 + 0] += mv[rr] * wr;
                acc[rr][q*3 + 1] += mv[rr] * wz;
                acc[rr][q*3 + 2] += mv[rr] * wn;
            }
        }
    }

    // x contribution (K = 64, 65)
    #pragma unroll
    for (int rr = 0; rr < 4; rr++) {
        int row = rowBase + ty*4 + rr;
        int n = row >> 6, b = row & 63;
        const float* xp = inputs + ((b*Tt + t)*Nn + n)*Dd;
        float x0 = xp[0], x1 = xp[1];
        const float* w64 = WihS + 64*192;
        const float* w65 = WihS + 65*192;
        #pragma unroll
        for (int q = 0; q < 4; q++) {
            int g = tx + q*16;
            acc[rr][q*3 + 0] += x0*w64[g]       + x1*w65[g];
            acc[rr][q*3 + 1] += x0*w64[64 + g]  + x1*w65[64 + g];
            acc[rr][q*3 + 2] += x0*w64[128 + g] + x1*w65[128 + g];
        }
    }

    int nxt = cur ^ 1;
    #pragma unroll
    for (int rr = 0; rr < 4; rr++) {
        int row = rowBase + ty*4 + rr;
        const float* gh = g_out1 + row*256;
        #pragma unroll
        for (int q = 0; q < 4; q++) {
            int g = tx + q*16;
            float ir  = acc[rr][q*3 + 0] + b_ih[g];
            float iz  = acc[rr][q*3 + 1] + b_ih[64 + g];
            float inn = acc[rr][q*3 + 2] + b_ih[128 + g];
            float hr = gh[g], hz = gh[64 + g], hn = gh[128 + g];
            float hold = g_h[cur][row*64 + g];
            float r = 1.f / (1.f + expf(-(ir + hr)));
            float z = 1.f / (1.f + expf(-(iz + hz)));
            float nn = tanhf(inn + r*hn);
            g_h[nxt][row*64 + g] = (1.f - z)*nn + z*hold;
        }
    }
}

// -------- final readout: out[b][hh][n] = h @ W_outT + b_out --------
__global__ void out_kernel(const float* __restrict__ W_out,
                           const float* __restrict__ b_out,
                           float* __restrict__ out) {
    __shared__ float wo[12*64];
    __shared__ float bo[12];
    int tid = threadIdx.x;
    for (int idx = tid; idx < 768; idx += 256) wo[idx] = W_out[idx];
    if (tid < 12) bo[tid] = b_out[tid];
    __syncthreads();
    int row = blockIdx.x * 256 + tid;   // 128 blocks x 256 = 32768 rows
    float accs[12];
    #pragma unroll
    for (int hh = 0; hh < 12; hh++) accs[hh] = bo[hh];
    for (int k = 0; k < 64; k++) {
        float hv = g_h[0][row*64 + k];
        #pragma unroll
        for (int hh = 0; hh < 12; hh++) accs[hh] += hv * wo[hh*64 + k];
    }
    int n = row >> 6, b = row & 63;
    #pragma unroll
    for (int hh = 0; hh < 12; hh++)
        out[(b*12 + hh)*512 + n] = accs[hh];
}

extern "C" void kernel_launch(void* const* d_in, const int* in_sizes, int n_in,
                              void* d_out, int out_size) {
    const float* inputs = (const float*)d_in[0];
    const float* h0     = (const float*)d_in[1];
    const float* adj    = (const float*)d_in[2];
    const float* W_msg  = (const float*)d_in[3];
    const float* b_msg  = (const float*)d_in[4];
    const float* W_ih   = (const float*)d_in[5];
    const float* W_hh   = (const float*)d_in[6];
    const float* b_ih   = (const float*)d_in[7];
    const float* b_hh   = (const float*)d_in[8];
    const float* W_out  = (const float*)d_in[9];
    const float* b_out  = (const float*)d_in[10];
    float* out = (float*)d_out;

    cudaFuncSetAttribute(gemm1_kernel, cudaFuncAttributeMaxDynamicSharedMemorySize, 67584);
    cudaFuncSetAttribute(gates_kernel, cudaFuncAttributeMaxDynamicSharedMemorySize, 68096);
    cudaFuncSetAttribute(agg_kernel,   cudaFuncAttributeMaxDynamicSharedMemorySize, 65536);

    prep_weights<<<115, 256>>>(W_msg, b_msg, W_ih, W_hh, b_hh);
    build_csc<<<512, 512>>>(adj);
    copy_h0<<<(NB*Rr + 255)/256, 256>>>(h0);

    for (int t = 0; t < Tt; t++) {
        int cur = t & 1;
        gemm1_kernel<<<dim3(256, 2), 256, 67584>>>(cur);
        agg_kernel<<<128, 256, 65536>>>();
        gates_kernel<<<512, 256, 68096>>>(inputs, b_ih, t, cur);
    }
    out_kernel<<<128, 256>>>(W_out, b_out, out);
}

// round 3
// speedup vs baseline: 1.3641x; 1.3641x over previous
#include <cuda_runtime.h>
#include <math.h>

#define Bb 64
#define Tt 12
#define Nn 512
#define Dd 2
#define Rr 64
#define NB (Nn*Bb)   // 32768 rows (row = n*64 + b)

// ---------------- device scratch ----------------
__device__ float g_h[2][NB*Rr];      // ping-pong hidden state
__device__ float g_s[NB*Rr];         // s = A^T h
__device__ float g_Wk[128*192];      // [k][plane*64+g]; k<64: W_hh (r,z,n); k>=64: W_combo (r,z,n)
__device__ float g_Wx[2*192];        // x weights: [d][o]
__device__ float g_cvec[192];        // b_msg @ W_ih_m^T
__device__ float g_csum[Nn];         // column sums of adj_pos
__device__ int   g_colj[Nn*Nn];      // CSC: column i at [i*512 ..]
__device__ float g_colw[Nn*Nn];
__device__ int   g_cnt[Nn];

// ---------------- f32x2 helpers ----------------
typedef unsigned long long ull;
#define FMA2(d, a, b) asm("fma.rn.f32x2 %0, %1, %2, %0;" : "+l"(d) : "l"(a), "l"(b))
#define PACK2(o, f)   asm("mov.b64 %0, {%1, %1};" : "=l"(o) : "f"(f))
#define UNPACK2(lo, hi, v) asm("mov.b64 {%0, %1}, %2;" : "=f"(lo), "=f"(hi) : "l"(v))

// ---------------- prep ----------------
__global__ void prep1(const float* __restrict__ W_hh,
                      const float* __restrict__ W_ih,
                      const float* __restrict__ b_msg) {
    int idx = blockIdx.x * 256 + threadIdx.x;
    if (idx < 12288) {                      // Wk h-part: g_Wk[k*192+o] = W_hh[o][k]
        int k = idx / 192, o = idx - k*192;
        g_Wk[idx] = W_hh[o*64 + k];
    } else if (idx < 12288 + 384) {         // Wx[d][o] = W_ih[o][64+d]
        int j = idx - 12288;
        int d = j / 192, o = j - d*192;
        g_Wx[idx - 12288] = W_ih[o*66 + 64 + d];
    } else if (idx < 12288 + 384 + 192) {   // cvec[o] = sum_m b_msg[m]*W_ih[o][m]
        int o = idx - 12288 - 384;
        float s = 0.f;
        for (int m = 0; m < 64; m++) s += b_msg[m] * W_ih[o*66 + m];
        g_cvec[o] = s;
    }
}

// W_combo[ks][o] = sum_m W_msg[m][ks] * W_ih[o][m]  -> g_Wk[(64+ks)*192 + o]
__global__ void prep2(const float* __restrict__ W_msg,
                      const float* __restrict__ W_ih) {
    int idx = blockIdx.x * 256 + threadIdx.x;
    if (idx >= 12288) return;
    int ks = idx / 192, o = idx - ks*192;
    float s = 0.f;
    for (int m = 0; m < 64; m++) s += W_msg[m*64 + ks] * W_ih[o*66 + m];
    g_Wk[(64 + ks)*192 + o] = s;
}

// Deterministic CSC build + column sums.
__global__ void build_csc(const float* __restrict__ adj) {
    int i = blockIdx.x;
    int j = threadIdx.x;                      // 512 threads
    float w = adj[j*Nn + i];
    bool p = (w > 0.f);
    unsigned mask = __ballot_sync(0xffffffffu, p);
    int warp = j >> 5, lane = j & 31;
    __shared__ int wcnt[16];
    __shared__ int wofs[16];
    __shared__ float ws[512];
    ws[j] = p ? w : 0.f;
    if (lane == 0) wcnt[warp] = __popc(mask);
    __syncthreads();
    if (j == 0) {
        int s = 0;
        for (int t = 0; t < 16; t++) { wofs[t] = s; s += wcnt[t]; }
        g_cnt[i] = s;
    }
    // deterministic tree reduction for csum
    for (int stride = 256; stride > 0; stride >>= 1) {
        __syncthreads();
        if (j < stride) ws[j] += ws[j + stride];
    }
    if (j == 0) g_csum[i] = ws[0];
    __syncthreads();
    if (p) {
        int pos = wofs[warp] + __popc(mask & ((1u << lane) - 1u));
        g_colj[i*Nn + pos] = j;
        g_colw[i*Nn + pos] = w;
    }
}

__global__ void copy_h0(const float* __restrict__ h0) {
    int idx = blockIdx.x * 256 + threadIdx.x;
    if (idx < NB * Rr) g_h[0][idx] = h0[idx];
}

// ---------------- per step kernel 1: s = A^T h ----------------
__global__ void agg_kernel(int cur) {
    extern __shared__ float hS[];   // [512][32]
    int b = blockIdx.x & 63, mc = blockIdx.x >> 6;
    int tid = threadIdx.x;
    const float* __restrict__ hg = g_h[cur];

    for (int idx = tid; idx < Nn*32; idx += 256) {
        int j = idx >> 5, mm = idx & 31;
        hS[idx] = hg[((j << 6) + b)*64 + (mc << 5) + mm];
    }
    __syncthreads();

    int lane = tid & 31, wid = tid >> 5;
    for (int i = wid; i < Nn; i += 8) {
        int cnt = g_cnt[i];
        const int*   cj = g_colj + i*Nn;
        const float* cw = g_colw + i*Nn;
        float acc = 0.f;
        for (int e0 = 0; e0 < cnt; e0 += 32) {
            int ee = e0 + lane;
            int   jv = (ee < cnt) ? cj[ee] : 0;
            float wv = (ee < cnt) ? cw[ee] : 0.f;
            int lim = min(32, cnt - e0);
            for (int kk = 0; kk < lim; kk++) {
                int   j = __shfl_sync(0xffffffffu, jv, kk);
                float w = __shfl_sync(0xffffffffu, wv, kk);
                acc += w * hS[j*32 + lane];
            }
        }
        g_s[((i << 6) + b)*64 + (mc << 5) + lane] = acc;
    }
}

// ---------------- per step kernel 2: fused GEMM + GRU ----------------
// block = node n (64 batch rows); 256 threads = 16 row-groups x 16 g-groups;
// thread: 4 rows x 4 gate-indices, packed f32x2 accumulators.
#define HP 65     // padded pitch for transposed tiles
__global__ __launch_bounds__(256, 2)
void gru_kernel(const float* __restrict__ inputs,
                const float* __restrict__ b_ih,
                const float* __restrict__ b_hh,
                int t, int cur) {
    extern __shared__ float sm[];
    float* wS  = sm;                 // 12288 (current weight stage)
    float* hT  = sm + 12288;         // [k][row] padded: 64*65
    float* sT  = hT + 64*HP;         // 64*65
    float* xW  = sT + 64*HP;         // 384
    float* xc  = xW + 384;           // 192
    float* xbi = xc + 192;           // 192
    float* xbh = xbi + 192;          // 192

    int n = blockIdx.x;
    int rowBase = n << 6;
    int tid = threadIdx.x;
    const float* __restrict__ hg = g_h[cur];

    // stage transposed tiles + small tables + stage-A weights
    for (int idx = tid; idx < 4096; idx += 256) {
        int r = idx >> 6, k = idx & 63;
        hT[k*HP + r] = hg[(rowBase + r)*64 + k];
        sT[k*HP + r] = g_s[(rowBase + r)*64 + k];
    }
    for (int idx = tid; idx < 3072; idx += 256)
        ((float4*)wS)[idx] = ((const float4*)g_Wk)[idx];
    for (int idx = tid; idx < 960; idx += 256) {
        float v;
        if (idx < 384)      v = g_Wx[idx];
        else if (idx < 576) v = g_cvec[idx - 384];
        else if (idx < 768) v = b_ih[idx - 576];
        else                v = b_hh[idx - 768];
        xW[idx] = v;   // xW is base of the contiguous small-table region
    }
    __syncthreads();

    int tx = tid & 15, ty = tid >> 4;
    int g0 = tx << 2;
    int r0 = ty << 2;

    ull aR[4][2], aZ[4][2], aN1[4][2], aN2[4][2];
    #pragma unroll
    for (int rr = 0; rr < 4; rr++) {
        aR[rr][0]=0; aR[rr][1]=0; aZ[rr][0]=0; aZ[rr][1]=0;
        aN1[rr][0]=0; aN1[rr][1]=0; aN2[rr][0]=0; aN2[rr][1]=0;
    }

    // stage A: h-planes (r, z, hn)
    #pragma unroll 4
    for (int k = 0; k < 64; k++) {
        const float* wk = wS + k*192 + g0;
        ulonglong2 wr = *(const ulonglong2*)(wk);
        ulonglong2 wz = *(const ulonglong2*)(wk + 64);
        ulonglong2 wn = *(const ulonglong2*)(wk + 128);
        #pragma unroll
        for (int rr = 0; rr < 4; rr++) {
            float hv = hT[k*HP + r0 + rr];
            ull h2; PACK2(h2, hv);
            FMA2(aR[rr][0],  h2, wr.x); FMA2(aR[rr][1],  h2, wr.y);
            FMA2(aZ[rr][0],  h2, wz.x); FMA2(aZ[rr][1],  h2, wz.y);
            FMA2(aN1[rr][0], h2, wn.x); FMA2(aN1[rr][1], h2, wn.y);
        }
    }
    __syncthreads();
    for (int idx = tid; idx < 3072; idx += 256)
        ((float4*)wS)[idx] = ((const float4*)g_Wk)[3072 + idx];
    __syncthreads();

    // stage B: s-planes (r, z, in)
    #pragma unroll 4
    for (int k = 0; k < 64; k++) {
        const float* wk = wS + k*192 + g0;
        ulonglong2 wr = *(const ulonglong2*)(wk);
        ulonglong2 wz = *(const ulonglong2*)(wk + 64);
        ulonglong2 wn = *(const ulonglong2*)(wk + 128);
        #pragma unroll
        for (int rr = 0; rr < 4; rr++) {
            float sv = sT[k*HP + r0 + rr];
            ull s2; PACK2(s2, sv);
            FMA2(aR[rr][0],  s2, wr.x); FMA2(aR[rr][1],  s2, wr.y);
            FMA2(aZ[rr][0],  s2, wz.x); FMA2(aZ[rr][1],  s2, wz.y);
            FMA2(aN2[rr][0], s2, wn.x); FMA2(aN2[rr][1], s2, wn.y);
        }
    }

    // epilogue: x contribution + biases + GRU nonlinearity
    float cs = g_csum[n];
    int nxt = cur ^ 1;
    #pragma unroll
    for (int rr = 0; rr < 4; rr++) {
        int rloc = r0 + rr;
        int row = rowBase + rloc;
        int b = rloc;
        const float* xp = inputs + ((b*Tt + t)*Nn + n)*Dd;
        float x0 = xp[0], x1 = xp[1];
        float vR[4], vZ[4], vN1[4], vN2[4], hnew[4];
        UNPACK2(vR[0],  vR[1],  aR[rr][0]);  UNPACK2(vR[2],  vR[3],  aR[rr][1]);
        UNPACK2(vZ[0],  vZ[1],  aZ[rr][0]);  UNPACK2(vZ[2],  vZ[3],  aZ[rr][1]);
        UNPACK2(vN1[0], vN1[1], aN1[rr][0]); UNPACK2(vN1[2], vN1[3], aN1[rr][1]);
        UNPACK2(vN2[0], vN2[1], aN2[rr][0]); UNPACK2(vN2[2], vN2[3], aN2[rr][1]);
        #pragma unroll
        for (int gl = 0; gl < 4; gl++) {
            int g = g0 + gl;
            float rpre = vR[gl] + x0*xW[g]        + x1*xW[192 + g]
                       + xbi[g] + xbh[g] + cs*xc[g];
            float zpre = vZ[gl] + x0*xW[64 + g]   + x1*xW[192 + 64 + g]
                       + xbi[64 + g] + xbh[64 + g] + cs*xc[64 + g];
            float inp  = vN2[gl] + x0*xW[128 + g] + x1*xW[192 + 128 + g]
                       + xbi[128 + g] + cs*xc[128 + g];
            float hnp  = vN1[gl] + xbh[128 + g];
            float rg = 1.f / (1.f + expf(-rpre));
            float zg = 1.f / (1.f + expf(-zpre));
            float nn = tanhf(inp + rg*hnp);
            float hold = hT[g*HP + rloc];
            hnew[gl] = (1.f - zg)*nn + zg*hold;
        }
        *(float4*)(g_h[nxt] + row*64 + g0) = *(float4*)hnew;
    }
}

// ---------------- final readout ----------------
__global__ void out_kernel(const float* __restrict__ W_out,
                           const float* __restrict__ b_out,
                           float* __restrict__ out) {
    __shared__ float wo[12*64];
    __shared__ float bo[12];
    int tid = threadIdx.x;
    for (int idx = tid; idx < 768; idx += 256) wo[idx] = W_out[idx];
    if (tid < 12) bo[tid] = b_out[tid];
    __syncthreads();
    int row = blockIdx.x * 256 + tid;
    float accs[12];
    #pragma unroll
    for (int hh = 0; hh < 12; hh++) accs[hh] = bo[hh];
    for (int k = 0; k < 64; k++) {
        float hv = g_h[0][row*64 + k];
        #pragma unroll
        for (int hh = 0; hh < 12; hh++) accs[hh] += hv * wo[hh*64 + k];
    }
    int n = row >> 6, b = row & 63;
    #pragma unroll
    for (int hh = 0; hh < 12; hh++)
        out[(b*12 + hh)*512 + n] = accs[hh];
}

extern "C" void kernel_launch(void* const* d_in, const int* in_sizes, int n_in,
                              void* d_out, int out_size) {
    const float* inputs = (const float*)d_in[0];
    const float* h0     = (const float*)d_in[1];
    const float* adj    = (const float*)d_in[2];
    const float* W_msg  = (const float*)d_in[3];
    const float* b_msg  = (const float*)d_in[4];
    const float* W_ih   = (const float*)d_in[5];
    const float* W_hh   = (const float*)d_in[6];
    const float* b_ih   = (const float*)d_in[7];
    const float* b_hh   = (const float*)d_in[8];
    const float* W_out  = (const float*)d_in[9];
    const float* b_out  = (const float*)d_in[10];
    float* out = (float*)d_out;

    static const int GRU_SMEM = (12288 + 2*64*HP + 960) * 4;
    cudaFuncSetAttribute(gru_kernel, cudaFuncAttributeMaxDynamicSharedMemorySize, GRU_SMEM);
    cudaFuncSetAttribute(agg_kernel, cudaFuncAttributeMaxDynamicSharedMemorySize, 65536);

    prep1<<<51, 256>>>(W_hh, W_ih, b_msg);
    prep2<<<48, 256>>>(W_msg, W_ih);
    build_csc<<<512, 512>>>(adj);
    copy_h0<<<(NB*Rr + 255)/256, 256>>>(h0);

    for (int t = 0; t < Tt; t++) {
        int cur = t & 1;
        agg_kernel<<<128, 256, 65536>>>(cur);
        gru_kernel<<<512, 256, GRU_SMEM>>>(inputs, b_ih, b_hh, t, cur);
    }
    out_kernel<<<128, 256>>>(W_out, b_out, out);
}

// round 4
// speedup vs baseline: 1.5285x; 1.1205x over previous
#include <cuda_runtime.h>
#include <math.h>

#define Bb 64
#define Tt 12
#define Nn 512
#define Dd 2
#define Rr 64
#define NB (Nn*Bb)   // 32768 rows (row = n*64 + b)

// ---------------- device scratch ----------------
__device__ float g_h[2][NB*Rr];      // ping-pong hidden state
__device__ float g_s[NB*Rr];         // s = A^T h
__device__ float g_Wk[128*192];      // [k][plane*64+g]; k<64: W_hh; k>=64: W_combo
__device__ float g_Wx[2*192];        // x weights
__device__ float g_cvec[192];        // b_msg @ W_ih_m^T
__device__ float g_csum[Nn];         // column sums of adj_pos
__device__ int   g_colj[Nn*Nn];      // CSC: column i at [i*512 ..]
__device__ float g_colw[Nn*Nn];
__device__ int   g_cnt[Nn];

// ---------------- f32x2 helpers ----------------
typedef unsigned long long ull;
#define FMA2(d, a, b) asm("fma.rn.f32x2 %0, %1, %2, %0;" : "+l"(d) : "l"(a), "l"(b))
#define PACK2(o, f)   asm("mov.b64 %0, {%1, %1};" : "=l"(o) : "f"(f))
#define UNPACK2(lo, hi, v) asm("mov.b64 {%0, %1}, %2;" : "=f"(lo), "=f"(hi) : "l"(v))

// ---------------- prep (merged) ----------------
__global__ void prep_kernel(const float* __restrict__ W_hh,
                            const float* __restrict__ W_ih,
                            const float* __restrict__ W_msg,
                            const float* __restrict__ b_msg) {
    int idx = blockIdx.x * 256 + threadIdx.x;
    if (idx < 12288) {                       // Wk h-part: [k][o] = W_hh[o][k]
        int k = idx / 192, o = idx - k*192;
        g_Wk[idx] = W_hh[o*64 + k];
    } else if (idx < 24576) {                // Wk s-part: combo
        int j = idx - 12288;
        int ks = j / 192, o = j - ks*192;
        float s = 0.f;
        for (int m = 0; m < 64; m++) s += W_msg[m*64 + ks] * W_ih[o*66 + m];
        g_Wk[idx] = s;
    } else if (idx < 24576 + 384) {          // Wx[d][o] = W_ih[o][64+d]
        int j = idx - 24576;
        int d = j / 192, o = j - d*192;
        g_Wx[j] = W_ih[o*66 + 64 + d];
    } else if (idx < 24576 + 384 + 192) {    // cvec[o] = sum_m b_msg[m]*W_ih[o][m]
        int o = idx - 24576 - 384;
        float s = 0.f;
        for (int m = 0; m < 64; m++) s += b_msg[m] * W_ih[o*66 + m];
        g_cvec[o] = s;
    }
}

// Deterministic CSC build + column sums.
__global__ void build_csc(const float* __restrict__ adj) {
    int i = blockIdx.x;
    int j = threadIdx.x;                      // 512 threads
    float w = adj[j*Nn + i];
    bool p = (w > 0.f);
    unsigned mask = __ballot_sync(0xffffffffu, p);
    int warp = j >> 5, lane = j & 31;
    __shared__ int wcnt[16];
    __shared__ int wofs[16];
    __shared__ float ws[512];
    ws[j] = p ? w : 0.f;
    if (lane == 0) wcnt[warp] = __popc(mask);
    __syncthreads();
    if (j == 0) {
        int s = 0;
        for (int t = 0; t < 16; t++) { wofs[t] = s; s += wcnt[t]; }
        g_cnt[i] = s;
    }
    for (int stride = 256; stride > 0; stride >>= 1) {
        __syncthreads();
        if (j < stride) ws[j] += ws[j + stride];
    }
    if (j == 0) g_csum[i] = ws[0];
    __syncthreads();
    if (p) {
        int pos = wofs[warp] + __popc(mask & ((1u << lane) - 1u));
        g_colj[i*Nn + pos] = j;
        g_colw[i*Nn + pos] = w;
    }
}

// ---------------- per step kernel 1: s = A^T h ----------------
// grid 512 = (b:64) x (mc:2) x (iq:4); warp handles 16 columns, no shuffles.
__global__ void agg_kernel(const float* __restrict__ h0, int t) {
    extern __shared__ float hS[];   // [512][32]
    const float* __restrict__ hsrc = (t == 0) ? h0 : g_h[t & 1];
    int bid = blockIdx.x;
    int b = bid & 63, mc = (bid >> 6) & 1, iq = bid >> 7;
    int tid = threadIdx.x;

    for (int idx = tid; idx < Nn*8; idx += 256) {
        int j = idx >> 3, q = idx & 7;
        ((float4*)hS)[idx] = *(const float4*)(hsrc + (((j << 6) + b) << 6) + (mc << 5) + (q << 2));
    }
    __syncthreads();

    int lane = tid & 31, wid = tid >> 5;
    #pragma unroll 1
    for (int c = 0; c < 16; c++) {
        int i = (iq << 7) + (c << 3) + wid;
        int cnt = g_cnt[i];
        const int*   cj = g_colj + i*Nn;
        const float* cw = g_colw + i*Nn;
        float a0 = 0.f, a1 = 0.f, a2 = 0.f, a3 = 0.f;
        int e = 0;
        for (; e + 4 <= cnt; e += 4) {
            int4   jv = *(const int4*)(cj + e);
            float4 wv = *(const float4*)(cw + e);
            a0 += wv.x * hS[(jv.x << 5) + lane];
            a1 += wv.y * hS[(jv.y << 5) + lane];
            a2 += wv.z * hS[(jv.z << 5) + lane];
            a3 += wv.w * hS[(jv.w << 5) + lane];
        }
        for (; e < cnt; e++)
            a0 += cw[e] * hS[(cj[e] << 5) + lane];
        g_s[(((i << 6) + b) << 6) + (mc << 5) + lane] = (a0 + a1) + (a2 + a3);
    }
}

// ---------------- per step kernel 2: fused GEMM + GRU ----------------
#define HP 68     // padded pitch (multiple of 4 for LDS.128)
__global__ __launch_bounds__(256, 2)
void gru_kernel(const float* __restrict__ inputs,
                const float* __restrict__ b_ih,
                const float* __restrict__ b_hh,
                const float* __restrict__ h0,
                int t) {
    extern __shared__ float sm[];
    float* wS  = sm;                 // 12288 (current weight stage)
    float* hT  = sm + 12288;         // [k][row] padded: 64*68
    float* sT  = hT + 64*HP;         // 64*68
    float* xW  = sT + 64*HP;         // 384
    float* xc  = xW + 384;           // 192
    float* xbi = xc + 192;           // 192
    float* xbh = xbi + 192;          // 192

    const float* __restrict__ hsrc = (t == 0) ? h0 : g_h[t & 1];
    float* __restrict__ hdst = g_h[(t + 1) & 1];

    int n = blockIdx.x;
    int rowBase = n << 6;
    int tid = threadIdx.x;

    for (int idx = tid; idx < 4096; idx += 256) {
        int r = idx >> 6, k = idx & 63;
        hT[k*HP + r] = hsrc[(rowBase + r)*64 + k];
        sT[k*HP + r] = g_s[(rowBase + r)*64 + k];
    }
    for (int idx = tid; idx < 3072; idx += 256)
        ((float4*)wS)[idx] = ((const float4*)g_Wk)[idx];
    for (int idx = tid; idx < 960; idx += 256) {
        float v;
        if (idx < 384)      v = g_Wx[idx];
        else if (idx < 576) v = g_cvec[idx - 384];
        else if (idx < 768) v = b_ih[idx - 576];
        else                v = b_hh[idx - 768];
        xW[idx] = v;
    }
    __syncthreads();

    int tx = tid & 15, ty = tid >> 4;
    int g0 = tx << 2;
    int r0 = ty << 2;

    ull aR[4][2], aZ[4][2], aN1[4][2], aN2[4][2];
    #pragma unroll
    for (int rr = 0; rr < 4; rr++) {
        aR[rr][0]=0; aR[rr][1]=0; aZ[rr][0]=0; aZ[rr][1]=0;
        aN1[rr][0]=0; aN1[rr][1]=0; aN2[rr][0]=0; aN2[rr][1]=0;
    }

    // stage A: h-planes (r, z, hn)
    #pragma unroll 4
    for (int k = 0; k < 64; k++) {
        const float* wk = wS + k*192 + g0;
        ulonglong2 wr = *(const ulonglong2*)(wk);
        ulonglong2 wz = *(const ulonglong2*)(wk + 64);
        ulonglong2 wn = *(const ulonglong2*)(wk + 128);
        float4 hv4 = *(const float4*)(hT + k*HP + r0);
        #pragma unroll
        for (int rr = 0; rr < 4; rr++) {
            float hv = (rr == 0) ? hv4.x : (rr == 1) ? hv4.y : (rr == 2) ? hv4.z : hv4.w;
            ull h2; PACK2(h2, hv);
            FMA2(aR[rr][0],  h2, wr.x); FMA2(aR[rr][1],  h2, wr.y);
            FMA2(aZ[rr][0],  h2, wz.x); FMA2(aZ[rr][1],  h2, wz.y);
            FMA2(aN1[rr][0], h2, wn.x); FMA2(aN1[rr][1], h2, wn.y);
        }
    }
    __syncthreads();
    for (int idx = tid; idx < 3072; idx += 256)
        ((float4*)wS)[idx] = ((const float4*)g_Wk)[3072 + idx];
    __syncthreads();

    // stage B: s-planes (r, z, in)
    #pragma unroll 4
    for (int k = 0; k < 64; k++) {
        const float* wk = wS + k*192 + g0;
        ulonglong2 wr = *(const ulonglong2*)(wk);
        ulonglong2 wz = *(const ulonglong2*)(wk + 64);
        ulonglong2 wn = *(const ulonglong2*)(wk + 128);
        float4 sv4 = *(const float4*)(sT + k*HP + r0);
        #pragma unroll
        for (int rr = 0; rr < 4; rr++) {
            float sv = (rr == 0) ? sv4.x : (rr == 1) ? sv4.y : (rr == 2) ? sv4.z : sv4.w;
            ull s2; PACK2(s2, sv);
            FMA2(aR[rr][0],  s2, wr.x); FMA2(aR[rr][1],  s2, wr.y);
            FMA2(aZ[rr][0],  s2, wz.x); FMA2(aZ[rr][1],  s2, wz.y);
            FMA2(aN2[rr][0], s2, wn.x); FMA2(aN2[rr][1], s2, wn.y);
        }
    }

    // epilogue: x contribution + biases + GRU nonlinearity
    float cs = g_csum[n];
    #pragma unroll
    for (int rr = 0; rr < 4; rr++) {
        int rloc = r0 + rr;
        int row = rowBase + rloc;
        int b = rloc;
        const float* xp = inputs + ((b*Tt + t)*Nn + n)*Dd;
        float x0 = xp[0], x1 = xp[1];
        float vR[4], vZ[4], vN1[4], vN2[4], hnew[4];
        UNPACK2(vR[0],  vR[1],  aR[rr][0]);  UNPACK2(vR[2],  vR[3],  aR[rr][1]);
        UNPACK2(vZ[0],  vZ[1],  aZ[rr][0]);  UNPACK2(vZ[2],  vZ[3],  aZ[rr][1]);
        UNPACK2(vN1[0], vN1[1], aN1[rr][0]); UNPACK2(vN1[2], vN1[3], aN1[rr][1]);
        UNPACK2(vN2[0], vN2[1], aN2[rr][0]); UNPACK2(vN2[2], vN2[3], aN2[rr][1]);
        #pragma unroll
        for (int gl = 0; gl < 4; gl++) {
            int g = g0 + gl;
            float rpre = vR[gl] + x0*xW[g]        + x1*xW[192 + g]
                       + xbi[g] + xbh[g] + cs*xc[g];
            float zpre = vZ[gl] + x0*xW[64 + g]   + x1*xW[192 + 64 + g]
                       + xbi[64 + g] + xbh[64 + g] + cs*xc[64 + g];
            float inp  = vN2[gl] + x0*xW[128 + g] + x1*xW[192 + 128 + g]
                       + xbi[128 + g] + cs*xc[128 + g];
            float hnp  = vN1[gl] + xbh[128 + g];
            float rg = 1.f / (1.f + expf(-rpre));
            float zg = 1.f / (1.f + expf(-zpre));
            float nn = tanhf(inp + rg*hnp);
            float hold = hT[g*HP + rloc];
            hnew[gl] = (1.f - zg)*nn + zg*hold;
        }
        *(float4*)(hdst + row*64 + g0) = *(float4*)hnew;
    }
}

// ---------------- final readout ----------------
__global__ void out_kernel(const float* __restrict__ W_out,
                           const float* __restrict__ b_out,
                           float* __restrict__ out) {
    __shared__ float wo[12*64];
    __shared__ float bo[12];
    int tid = threadIdx.x;
    for (int idx = tid; idx < 768; idx += 256) wo[idx] = W_out[idx];
    if (tid < 12) bo[tid] = b_out[tid];
    __syncthreads();
    int row = blockIdx.x * 256 + tid;
    float accs[12];
    #pragma unroll
    for (int hh = 0; hh < 12; hh++) accs[hh] = bo[hh];
    for (int k = 0; k < 64; k++) {
        float hv = g_h[0][row*64 + k];
        #pragma unroll
        for (int hh = 0; hh < 12; hh++) accs[hh] += hv * wo[hh*64 + k];
    }
    int n = row >> 6, b = row & 63;
    #pragma unroll
    for (int hh = 0; hh < 12; hh++)
        out[(b*12 + hh)*512 + n] = accs[hh];
}

extern "C" void kernel_launch(void* const* d_in, const int* in_sizes, int n_in,
                              void* d_out, int out_size) {
    const float* inputs = (const float*)d_in[0];
    const float* h0     = (const float*)d_in[1];
    const float* adj    = (const float*)d_in[2];
    const float* W_msg  = (const float*)d_in[3];
    const float* b_msg  = (const float*)d_in[4];
    const float* W_ih   = (const float*)d_in[5];
    const float* W_hh   = (const float*)d_in[6];
    const float* b_ih   = (const float*)d_in[7];
    const float* b_hh   = (const float*)d_in[8];
    const float* W_out  = (const float*)d_in[9];
    const float* b_out  = (const float*)d_in[10];
    float* out = (float*)d_out;

    static const int GRU_SMEM = (12288 + 2*64*HP + 960) * 4;
    cudaFuncSetAttribute(gru_kernel, cudaFuncAttributeMaxDynamicSharedMemorySize, GRU_SMEM);
    cudaFuncSetAttribute(agg_kernel, cudaFuncAttributeMaxDynamicSharedMemorySize, 65536);

    prep_kernel<<<99, 256>>>(W_hh, W_ih, W_msg, b_msg);
    build_csc<<<512, 512>>>(adj);

    // h for step t: t==0 -> h0 (input), else g_h[t&1]; gru(t) writes g_h[(t+1)&1].
    // t=11 writes g_h[0]; out_kernel reads g_h[0].
    for (int t = 0; t < Tt; t++) {
        agg_kernel<<<512, 256, 65536>>>(h0, t);
        gru_kernel<<<512, 256, GRU_SMEM>>>(inputs, b_ih, b_hh, h0, t);
    }
    out_kernel<<<128, 256>>>(W_out, b_out, out);
}

// round 5
// speedup vs baseline: 1.5393x; 1.0071x over previous
#include <cuda_runtime.h>
#include <math.h>

#define Bb 64
#define Tt 12
#define Nn 512
#define Dd 2
#define Rr 64
#define NB (Nn*Bb)   // 32768 rows (row = n*64 + b)

// ---------------- device scratch ----------------
__device__ float g_h[2][NB*Rr];      // ping-pong hidden state
__device__ float g_s[NB*Rr];         // s = A^T h
__device__ float g_W2[130*192];      // [k][plane*64+g]; k<64: W_hh, 64..127: combo, 128..129: Wx
__device__ float g_cvec[192];        // b_msg @ W_ih_m^T
__device__ float g_csum[Nn];         // column sums of adj_pos
__device__ int   g_colj[Nn*Nn];      // CSC: column i at [i*512 ..]
__device__ float g_colw[Nn*Nn];
__device__ int   g_cnt[Nn];

// ---------------- f32x2 helpers ----------------
typedef unsigned long long ull;
#define FMA2(d, a, b) asm("fma.rn.f32x2 %0, %1, %2, %0;" : "+l"(d) : "l"(a), "l"(b))
#define PACK2(o, f)   asm("mov.b64 %0, {%1, %1};" : "=l"(o) : "f"(f))
#define UNPACK2(lo, hi, v) asm("mov.b64 {%0, %1}, %2;" : "=f"(lo), "=f"(hi) : "l"(v))

// ---------------- prep ----------------
__global__ void prep_kernel(const float* __restrict__ W_hh,
                            const float* __restrict__ W_ih,
                            const float* __restrict__ W_msg,
                            const float* __restrict__ b_msg) {
    int idx = blockIdx.x * 256 + threadIdx.x;
    if (idx < 12288) {                       // h-part: [k][o] = W_hh[o][k]
        int k = idx / 192, o = idx - k*192;
        g_W2[idx] = W_hh[o*64 + k];
    } else if (idx < 24576) {                // s-part: combo[ks][o]
        int j = idx - 12288;
        int ks = j / 192, o = j - ks*192;
        float s = 0.f;
        for (int m = 0; m < 64; m++) s += W_msg[m*64 + ks] * W_ih[o*66 + m];
        g_W2[idx] = s;
    } else if (idx < 24576 + 384) {          // x rows: [128+d][o] = W_ih[o][64+d]
        int j = idx - 24576;
        int d = j / 192, o = j - d*192;
        g_W2[(128 + d)*192 + o] = W_ih[o*66 + 64 + d];
    } else if (idx < 24960 + 192) {          // cvec[o] = sum_m b_msg[m]*W_ih[o][m]
        int o = idx - 24960;
        float s = 0.f;
        for (int m = 0; m < 64; m++) s += b_msg[m] * W_ih[o*66 + m];
        g_cvec[o] = s;
    }
}

// Deterministic CSC build + column sums.
__global__ void build_csc(const float* __restrict__ adj) {
    int i = blockIdx.x;
    int j = threadIdx.x;                      // 512 threads
    float w = adj[j*Nn + i];
    bool p = (w > 0.f);
    unsigned mask = __ballot_sync(0xffffffffu, p);
    int warp = j >> 5, lane = j & 31;
    __shared__ int wcnt[16];
    __shared__ int wofs[16];
    __shared__ float ws[512];
    ws[j] = p ? w : 0.f;
    if (lane == 0) wcnt[warp] = __popc(mask);
    __syncthreads();
    if (j == 0) {
        int s = 0;
        for (int t = 0; t < 16; t++) { wofs[t] = s; s += wcnt[t]; }
        g_cnt[i] = s;
    }
    for (int stride = 256; stride > 0; stride >>= 1) {
        __syncthreads();
        if (j < stride) ws[j] += ws[j + stride];
    }
    if (j == 0) g_csum[i] = ws[0];
    __syncthreads();
    if (p) {
        int pos = wofs[warp] + __popc(mask & ((1u << lane) - 1u));
        g_colj[i*Nn + pos] = j;
        g_colw[i*Nn + pos] = w;
    }
}

// ---------------- per step kernel 1: s = A^T h ----------------
// grid 512 = (b:64) x (mc:2) x (iq:4); 8-way unrolled, MLP=8, no shuffles.
__global__ __launch_bounds__(256, 3)
void agg_kernel(const float* __restrict__ h0, int t) {
    extern __shared__ float hS[];   // [512][32]
    const float* __restrict__ hsrc = (t == 0) ? h0 : g_h[t & 1];
    int bid = blockIdx.x;
    int b = bid & 63, mc = (bid >> 6) & 1, iq = bid >> 7;
    int tid = threadIdx.x;

    for (int idx = tid; idx < Nn*8; idx += 256) {
        int j = idx >> 3, q = idx & 7;
        ((float4*)hS)[idx] = *(const float4*)(hsrc + (((j << 6) + b) << 6) + (mc << 5) + (q << 2));
    }
    __syncthreads();

    int lane = tid & 31, wid = tid >> 5;
    #pragma unroll 1
    for (int c = 0; c < 16; c++) {
        int i = (iq << 7) + (c << 3) + wid;
        int cnt = g_cnt[i];
        const int*   cj = g_colj + i*Nn;
        const float* cw = g_colw + i*Nn;
        float a0=0.f,a1=0.f,a2=0.f,a3=0.f,a4=0.f,a5=0.f,a6=0.f,a7=0.f;
        int e = 0;
        for (; e + 8 <= cnt; e += 8) {
            int4   j0 = *(const int4*)(cj + e);
            int4   j1 = *(const int4*)(cj + e + 4);
            float4 w0 = *(const float4*)(cw + e);
            float4 w1 = *(const float4*)(cw + e + 4);
            a0 += w0.x * hS[(j0.x << 5) + lane];
            a1 += w0.y * hS[(j0.y << 5) + lane];
            a2 += w0.z * hS[(j0.z << 5) + lane];
            a3 += w0.w * hS[(j0.w << 5) + lane];
            a4 += w1.x * hS[(j1.x << 5) + lane];
            a5 += w1.y * hS[(j1.y << 5) + lane];
            a6 += w1.z * hS[(j1.z << 5) + lane];
            a7 += w1.w * hS[(j1.w << 5) + lane];
        }
        for (; e < cnt; e++)
            a0 += cw[e] * hS[(cj[e] << 5) + lane];
        g_s[(((i << 6) + b) << 6) + (mc << 5) + lane] =
            ((a0 + a1) + (a2 + a3)) + ((a4 + a5) + (a6 + a7));
    }
}

// ---------------- per step kernel 2: fused GEMM + GRU ----------------
// grid 1024 = (n:512) x (gate-half:2); block: 64 rows x 96 outputs.
// thread: 4 rows x 2 gates x (r,z,n-h,n-s) = 16 packed accumulators.
// x-term folded into the s-GEMM as k-rows 64,65.
#define HP 68
__global__ __launch_bounds__(256, 2)
void gru_kernel(const float* __restrict__ inputs,
                const float* __restrict__ b_ih,
                const float* __restrict__ b_hh,
                const float* __restrict__ h0,
                int t) {
    extern __shared__ float sm[];
    float* wS = sm;                 // [130][96] = 12480
    float* hT = sm + 12480;         // [64][HP]
    float* sT = hT + 64*HP;         // [66][HP] (rows 64,65 = x)
    float* tb = sT + 66*HP;         // 576: bi(192) | bh(192) | cv(192)

    const float* __restrict__ hsrc = (t == 0) ? h0 : g_h[t & 1];
    float* __restrict__ hdst = g_h[(t + 1) & 1];

    int n = blockIdx.x >> 1;
    int gbase = (blockIdx.x & 1) << 5;   // 0 or 32 (per-plane gate offset)
    int rowBase = n << 6;
    int tid = threadIdx.x;

    for (int idx = tid; idx < 4096; idx += 256) {
        int r = idx >> 6, k = idx & 63;
        hT[k*HP + r] = hsrc[(rowBase + r)*64 + k];
        sT[k*HP + r] = g_s[(rowBase + r)*64 + k];
    }
    if (tid < 64) {
        float2 x = *(const float2*)(inputs + ((tid*Tt + t)*Nn + n)*Dd);
        sT[64*HP + tid] = x.x;
        sT[65*HP + tid] = x.y;
    }
    for (int idx = tid; idx < 12480; idx += 256) {
        int k = idx / 96;
        int c = idx - k*96;
        int plane = c >> 5, gl = c & 31;
        wS[idx] = g_W2[k*192 + plane*64 + gbase + gl];
    }
    for (int idx = tid; idx < 576; idx += 256) {
        float v = (idx < 192) ? b_ih[idx]
                : (idx < 384) ? b_hh[idx - 192]
                : g_cvec[idx - 384];
        tb[idx] = v;
    }
    __syncthreads();

    int tx = tid & 15, ty = tid >> 4;
    int r0 = ty << 2;
    int gofs = tx << 1;                  // 0..30, 2 gates per thread

    ull aR[4], aZ[4], aN1[4], aN2[4];
    #pragma unroll
    for (int rr = 0; rr < 4; rr++) { aR[rr]=0; aZ[rr]=0; aN1[rr]=0; aN2[rr]=0; }

    // h-part: planes r,z,hn
    #pragma unroll 4
    for (int k = 0; k < 64; k++) {
        const float* wk = wS + k*96 + gofs;
        ull wr = *(const ull*)(wk);
        ull wz = *(const ull*)(wk + 32);
        ull wn = *(const ull*)(wk + 64);
        float4 hv4 = *(const float4*)(hT + k*HP + r0);
        #pragma unroll
        for (int rr = 0; rr < 4; rr++) {
            float hv = (rr==0)?hv4.x:(rr==1)?hv4.y:(rr==2)?hv4.z:hv4.w;
            ull h2; PACK2(h2, hv);
            FMA2(aR[rr], h2, wr);
            FMA2(aZ[rr], h2, wz);
            FMA2(aN1[rr], h2, wn);
        }
    }
    // s-part (+x rows 64,65): planes r,z,in
    #pragma unroll 4
    for (int k = 0; k < 66; k++) {
        const float* wk = wS + (64 + k)*96 + gofs;
        ull wr = *(const ull*)(wk);
        ull wz = *(const ull*)(wk + 32);
        ull wn = *(const ull*)(wk + 64);
        float4 sv4 = *(const float4*)(sT + k*HP + r0);
        #pragma unroll
        for (int rr = 0; rr < 4; rr++) {
            float sv = (rr==0)?sv4.x:(rr==1)?sv4.y:(rr==2)?sv4.z:sv4.w;
            ull s2; PACK2(s2, sv);
            FMA2(aR[rr], s2, wr);
            FMA2(aZ[rr], s2, wz);
            FMA2(aN2[rr], s2, wn);
        }
    }

    // epilogue: biases + cvec + GRU nonlinearity
    float cs = g_csum[n];
    #pragma unroll
    for (int rr = 0; rr < 4; rr++) {
        int rloc = r0 + rr;
        int row = rowBase + rloc;
        float vR[2], vZ[2], vN1[2], vN2[2], hnew[2];
        UNPACK2(vR[0],  vR[1],  aR[rr]);
        UNPACK2(vZ[0],  vZ[1],  aZ[rr]);
        UNPACK2(vN1[0], vN1[1], aN1[rr]);
        UNPACK2(vN2[0], vN2[1], aN2[rr]);
        #pragma unroll
        for (int j = 0; j < 2; j++) {
            int g = gbase + gofs + j;        // per-plane gate index 0..63
            float rpre = vR[j]  + tb[g]        + tb[192 + g]        + cs*tb[384 + g];
            float zpre = vZ[j]  + tb[64 + g]   + tb[192 + 64 + g]   + cs*tb[384 + 64 + g];
            float inp  = vN2[j] + tb[128 + g]                        + cs*tb[384 + 128 + g];
            float hnp  = vN1[j] + tb[192 + 128 + g];
            float rg = 1.f / (1.f + expf(-rpre));
            float zg = 1.f / (1.f + expf(-zpre));
            float nn = tanhf(inp + rg*hnp);
            float hold = hT[g*HP + rloc];
            hnew[j] = (1.f - zg)*nn + zg*hold;
        }
        *(float2*)(hdst + row*64 + gbase + gofs) = *(float2*)hnew;
    }
}

// ---------------- final readout ----------------
__global__ void out_kernel(const float* __restrict__ W_out,
                           const float* __restrict__ b_out,
                           float* __restrict__ out) {
    __shared__ float wo[12*64];
    __shared__ float bo[12];
    int tid = threadIdx.x;
    for (int idx = tid; idx < 768; idx += 256) wo[idx] = W_out[idx];
    if (tid < 12) bo[tid] = b_out[tid];
    __syncthreads();
    int row = blockIdx.x * 256 + tid;
    float accs[12];
    #pragma unroll
    for (int hh = 0; hh < 12; hh++) accs[hh] = bo[hh];
    for (int k = 0; k < 64; k++) {
        float hv = g_h[0][row*64 + k];
        #pragma unroll
        for (int hh = 0; hh < 12; hh++) accs[hh] += hv * wo[hh*64 + k];
    }
    int n = row >> 6, b = row & 63;
    #pragma unroll
    for (int hh = 0; hh < 12; hh++)
        out[(b*12 + hh)*512 + n] = accs[hh];
}

extern "C" void kernel_launch(void* const* d_in, const int* in_sizes, int n_in,
                              void* d_out, int out_size) {
    const float* inputs = (const float*)d_in[0];
    const float* h0     = (const float*)d_in[1];
    const float* adj    = (const float*)d_in[2];
    const float* W_msg  = (const float*)d_in[3];
    const float* b_msg  = (const float*)d_in[4];
    const float* W_ih   = (const float*)d_in[5];
    const float* W_hh   = (const float*)d_in[6];
    const float* b_ih   = (const float*)d_in[7];
    const float* b_hh   = (const float*)d_in[8];
    const float* W_out  = (const float*)d_in[9];
    const float* b_out  = (const float*)d_in[10];
    float* out = (float*)d_out;

    static const int GRU_SMEM = (12480 + 64*HP + 66*HP + 576) * 4;   // 87584 B
    cudaFuncSetAttribute(gru_kernel, cudaFuncAttributeMaxDynamicSharedMemorySize, GRU_SMEM);
    cudaFuncSetAttribute(agg_kernel, cudaFuncAttributeMaxDynamicSharedMemorySize, 65536);

    prep_kernel<<<99, 256>>>(W_hh, W_ih, W_msg, b_msg);
    build_csc<<<512, 512>>>(adj);

    // t=11 writes g_h[0]; out_kernel reads g_h[0].
    for (int t = 0; t < Tt; t++) {
        agg_kernel<<<512, 256, 65536>>>(h0, t);
        gru_kernel<<<1024, 256, GRU_SMEM>>>(inputs, b_ih, b_hh, h0, t);
    }
    out_kernel<<<128, 256>>>(W_out, b_out, out);
}